// round 2
// baseline (speedup 1.0000x reference)
#include <cuda_runtime.h>
#include <stdint.h>

#define Bn 32
#define Nn 512
#define Pn 128

// Scratch (static device globals: allocation-free)
__device__ float g_mw[Bn * Nn * Pn];   // mu @ W2, 8 MB
__device__ float g_vp[Pn];
__device__ float g_vn[Pn];
__device__ float g_cb[Pn];             // b1 + b2 + b3

// ---------------------------------------------------------------------------
// Kernel P: vp[p] = sum_q relu(t[q]) * W3[q][p]; vn likewise; cb = b1+b2+b3
// ---------------------------------------------------------------------------
__global__ void prep_kernel(const float* __restrict__ W3,
                            const float* __restrict__ theta4,
                            const float* __restrict__ b1,
                            const float* __restrict__ b2,
                            const float* __restrict__ b3) {
    int p = threadIdx.x;  // 128 threads
    float vp = 0.f, vn = 0.f;
    #pragma unroll 8
    for (int q = 0; q < Pn; ++q) {
        float t = theta4[q];
        float w = W3[q * Pn + p];
        vp += fmaxf(t, 0.f) * w;
        vn += fmaxf(-t, 0.f) * w;
    }
    g_vp[p] = vp;
    g_vn[p] = vn;
    g_cb[p] = b1[p] + b2[p] + b3[p];
}

// ---------------------------------------------------------------------------
// Kernel M: g_mw = mu @ W2   (16384 x 128) @ (128 x 128), fp32 tiled GEMM
// Block: 64 rows, 256 threads; thread tile 4x8; BK=32.
// ---------------------------------------------------------------------------
__global__ __launch_bounds__(256) void mw_kernel(const float* __restrict__ mu,
                                                 const float* __restrict__ W2) {
    __shared__ float As[32 * 65];    // [k][m], padded (bank-clean)
    __shared__ float Bs[32 * 128];   // [k][n]

    int tid = threadIdx.x;
    int tx = tid & 15;   // 16 col-groups of 8
    int ty = tid >> 4;   // 16 row-groups of 4
    int r0 = blockIdx.x * 64;

    float acc[4][8];
    #pragma unroll
    for (int u = 0; u < 4; ++u)
        #pragma unroll
        for (int v = 0; v < 8; ++v) acc[u][v] = 0.f;

    for (int kb = 0; kb < 4; ++kb) {
        int k0 = kb * 32;
        // Stage A transposed: As[k][m] = mu[r0+m][k0+k]  (coalesced over k)
        #pragma unroll
        for (int s = 0; s < 8; ++s) {
            int idx = tid + s * 256;       // 0..2047
            int k = idx & 31;
            int m = idx >> 5;
            As[k * 65 + m] = mu[(r0 + m) * Pn + k0 + k];
        }
        // Stage B: Bs[k][n] (float4, coalesced)
        #pragma unroll
        for (int s = 0; s < 4; ++s) {
            int idx = tid + s * 256;       // 0..1023
            int k = idx >> 5;
            int c = idx & 31;
            *(float4*)&Bs[k * 128 + c * 4] =
                *(const float4*)&W2[(k0 + k) * Pn + c * 4];
        }
        __syncthreads();

        #pragma unroll
        for (int k = 0; k < 32; ++k) {
            float a0 = As[k * 65 + ty * 4 + 0];
            float a1 = As[k * 65 + ty * 4 + 1];
            float a2 = As[k * 65 + ty * 4 + 2];
            float a3 = As[k * 65 + ty * 4 + 3];
            float4 bb0 = *(const float4*)&Bs[k * 128 + tx * 8];
            float4 bb1 = *(const float4*)&Bs[k * 128 + tx * 8 + 4];
            float bv[8] = {bb0.x, bb0.y, bb0.z, bb0.w, bb1.x, bb1.y, bb1.z, bb1.w};
            float av[4] = {a0, a1, a2, a3};
            #pragma unroll
            for (int u = 0; u < 4; ++u)
                #pragma unroll
                for (int v = 0; v < 8; ++v)
                    acc[u][v] += av[u] * bv[v];
        }
        __syncthreads();
    }

    #pragma unroll
    for (int u = 0; u < 4; ++u) {
        int row = r0 + ty * 4 + u;
        float4 o0 = {acc[u][0], acc[u][1], acc[u][2], acc[u][3]};
        float4 o1 = {acc[u][4], acc[u][5], acc[u][6], acc[u][7]};
        *(float4*)&g_mw[row * Pn + tx * 8]     = o0;
        *(float4*)&g_mw[row * Pn + tx * 8 + 4] = o1;
    }
}

// ---------------------------------------------------------------------------
// Kernel A: fused sparse aggregation + pos/neg + epilogue
// Grid: (8 j-tiles, 32 batches). 512 threads = 16 warps; warp handles 4 j's.
// out[b,j,p] = relu( x[b,j]*W1[p] + sum_{i: adj[b,i,j]!=0} mw[b,i,p]
//                    + pos[b,j]*vp[p] + neg[b,j]*vn[p] + cb[p] )
// ---------------------------------------------------------------------------
__global__ __launch_bounds__(512) void agg_kernel(
    const float* __restrict__ adj, const float* __restrict__ weight,
    const float* __restrict__ x, const float* __restrict__ W1,
    float* __restrict__ out) {
    extern __shared__ float smem[];
    float* mwS  = smem;                   // 128*128
    float* adjS = mwS + 128 * 128;        // 128 rows, stride 65 ([i][j])
    float* wS   = adjS + 128 * 65;        // same layout
    float* W1s  = wS + 128 * 65;          // 128
    float* vps  = W1s + 128;
    float* vns  = vps + 128;
    float* cbs  = vns + 128;

    int tid = threadIdx.x;
    int warp = tid >> 5;
    int lane = tid & 31;
    int b = blockIdx.y;
    int j0 = blockIdx.x * 64;

    if (tid < 128) {
        W1s[tid] = W1[tid];
        vps[tid] = g_vp[tid];
        vns[tid] = g_vn[tid];
        cbs[tid] = g_cb[tid];
    }

    const float* adj_b = adj + (size_t)b * Nn * Nn;
    const float* w_b   = weight + (size_t)b * Nn * Nn;
    const float* mw_b  = g_mw + (size_t)b * Nn * Pn;

    float4 acc[4];
    float pos[4], neg[4];
    #pragma unroll
    for (int jj = 0; jj < 4; ++jj) {
        acc[jj].x = acc[jj].y = acc[jj].z = acc[jj].w = 0.f;
        pos[jj] = 0.f;
        neg[jj] = 0.f;
    }

    for (int chunk = 0; chunk < 4; ++chunk) {
        int i0 = chunk * 128;
        __syncthreads();  // previous chunk's smem reads done (also covers W1s init)

        // Stage mw chunk: 128 x 128 floats (float4, coalesced)
        #pragma unroll
        for (int s = 0; s < 8; ++s) {
            int idx = tid + s * 512;      // 0..4095
            int row = idx >> 5;
            int c = idx & 31;
            *(float4*)&mwS[row * 128 + c * 4] =
                *(const float4*)&mw_b[(i0 + row) * Pn + c * 4];
        }
        // Stage adj + weight tile: [128 i][64 j], stride-65 (bank-clean scans)
        #pragma unroll
        for (int s = 0; s < 4; ++s) {
            int idx = tid + s * 512;      // 0..2047
            int row = idx >> 4;
            int jc = idx & 15;
            size_t g = (size_t)(i0 + row) * Nn + j0 + jc * 4;
            float4 a = *(const float4*)&adj_b[g];
            float4 w = *(const float4*)&w_b[g];
            int base = row * 65 + jc * 4;
            adjS[base + 0] = a.x; adjS[base + 1] = a.y;
            adjS[base + 2] = a.z; adjS[base + 3] = a.w;
            wS[base + 0] = w.x; wS[base + 1] = w.y;
            wS[base + 2] = w.z; wS[base + 3] = w.w;
        }
        __syncthreads();

        // Warp-cooperative nonzero scan + gather-accumulate
        #pragma unroll
        for (int jj = 0; jj < 4; ++jj) {
            int j = warp * 4 + jj;
            float4 a4 = acc[jj];
            float pj = pos[jj], nj = neg[jj];
            for (int base = 0; base < 128; base += 32) {
                float a = adjS[(base + lane) * 65 + j];  // conflict-free
                unsigned m = __ballot_sync(0xffffffffu, a != 0.f);
                while (m) {
                    int i = base + (__ffs((int)m) - 1);
                    m &= m - 1;
                    float w = wS[i * 65 + j];            // broadcast
                    pj += fmaxf(w, 0.f);
                    nj += fmaxf(-w, 0.f);
                    float4 v = *(const float4*)&mwS[i * 128 + (lane << 2)];
                    a4.x += v.x; a4.y += v.y; a4.z += v.z; a4.w += v.w;
                }
            }
            acc[jj] = a4;
            pos[jj] = pj;
            neg[jj] = nj;
        }
    }

    // Fused epilogue: unit1 + unit2 + unit3 + relu, float4 coalesced store
    #pragma unroll
    for (int jj = 0; jj < 4; ++jj) {
        int gj = j0 + warp * 4 + jj;
        float xv = x[b * Nn + gj];
        int p = lane << 2;
        float4 o;
        o.x = fmaxf(xv * W1s[p + 0] + acc[jj].x + pos[jj] * vps[p + 0] + neg[jj] * vns[p + 0] + cbs[p + 0], 0.f);
        o.y = fmaxf(xv * W1s[p + 1] + acc[jj].y + pos[jj] * vps[p + 1] + neg[jj] * vns[p + 1] + cbs[p + 1], 0.f);
        o.z = fmaxf(xv * W1s[p + 2] + acc[jj].z + pos[jj] * vps[p + 2] + neg[jj] * vns[p + 2] + cbs[p + 2], 0.f);
        o.w = fmaxf(xv * W1s[p + 3] + acc[jj].w + pos[jj] * vps[p + 3] + neg[jj] * vns[p + 3] + cbs[p + 3], 0.f);
        *(float4*)&out[((size_t)b * Nn + gj) * Pn + p] = o;
    }
}

// ---------------------------------------------------------------------------
extern "C" void kernel_launch(void* const* d_in, const int* in_sizes, int n_in,
                              void* d_out, int out_size) {
    const float* x      = (const float*)d_in[0];
    const float* mu     = (const float*)d_in[1];
    const float* weight = (const float*)d_in[2];
    const float* adj    = (const float*)d_in[3];
    const float* W1     = (const float*)d_in[4];
    const float* b1     = (const float*)d_in[5];
    const float* W2     = (const float*)d_in[6];
    const float* b2     = (const float*)d_in[7];
    const float* W3     = (const float*)d_in[8];
    const float* b3     = (const float*)d_in[9];
    const float* theta4 = (const float*)d_in[10];
    float* out = (float*)d_out;

    const int smem_bytes = (128 * 128 + 2 * 128 * 65 + 4 * 128) * 4;  // 134144
    cudaFuncSetAttribute(agg_kernel, cudaFuncAttributeMaxDynamicSharedMemorySize,
                         smem_bytes);

    prep_kernel<<<1, 128>>>(W3, theta4, b1, b2, b3);
    mw_kernel<<<Bn * Nn / 64, 256>>>(mu, W2);
    dim3 grid(Nn / 64, Bn);
    agg_kernel<<<grid, 512, smem_bytes>>>(adj, weight, x, W1, out);
}

// round 3
// speedup vs baseline: 1.2672x; 1.2672x over previous
#include <cuda_runtime.h>
#include <stdint.h>

#define Bn 32
#define Nn 512
#define Pn 128

// Scratch (static device globals: allocation-free)
__device__ float g_mw[Bn * Nn * Pn];   // mu @ W2, 8 MB
__device__ float g_vp[Pn];
__device__ float g_vn[Pn];
__device__ float g_cb[Pn];             // b1 + b2 + b3

// ---------------------------------------------------------------------------
// Kernel M: g_mw = mu @ W2   (16384 x 128) @ (128 x 128), fp32 tiled GEMM.
// Last block (blockIdx.x == gridDim.x-1) instead computes vp/vn/cb (prep),
// removing the former serialized prep launch.
// ---------------------------------------------------------------------------
__global__ __launch_bounds__(256) void mw_kernel(const float* __restrict__ mu,
                                                 const float* __restrict__ W2,
                                                 const float* __restrict__ W3,
                                                 const float* __restrict__ theta4,
                                                 const float* __restrict__ b1,
                                                 const float* __restrict__ b2,
                                                 const float* __restrict__ b3) {
    if (blockIdx.x == gridDim.x - 1) {
        // prep: vp[p] = sum_q relu(t[q])*W3[q][p]; vn likewise; cb = b1+b2+b3
        int p = threadIdx.x;
        if (p < Pn) {
            float vp = 0.f, vn = 0.f;
            #pragma unroll 8
            for (int q = 0; q < Pn; ++q) {
                float t = theta4[q];
                float w = W3[q * Pn + p];
                vp += fmaxf(t, 0.f) * w;
                vn += fmaxf(-t, 0.f) * w;
            }
            g_vp[p] = vp;
            g_vn[p] = vn;
            g_cb[p] = b1[p] + b2[p] + b3[p];
        }
        return;
    }

    __shared__ float As[32 * 65];    // [k][m], padded
    __shared__ float Bs[32 * 128];   // [k][n]

    int tid = threadIdx.x;
    int tx = tid & 15;   // 16 col-groups of 8
    int ty = tid >> 4;   // 16 row-groups of 4
    int r0 = blockIdx.x * 64;

    float acc[4][8];
    #pragma unroll
    for (int u = 0; u < 4; ++u)
        #pragma unroll
        for (int v = 0; v < 8; ++v) acc[u][v] = 0.f;

    for (int kb = 0; kb < 4; ++kb) {
        int k0 = kb * 32;
        // Stage A transposed via float4: As[k][m] = mu[r0+m][k0+k]
        #pragma unroll
        for (int s = 0; s < 2; ++s) {
            int idx = tid + s * 256;           // 0..511
            int m = idx >> 3;                  // 0..63
            int kq = idx & 7;                  // k-quad 0..7
            float4 f = *(const float4*)&mu[(r0 + m) * Pn + k0 + kq * 4];
            As[(kq * 4 + 0) * 65 + m] = f.x;
            As[(kq * 4 + 1) * 65 + m] = f.y;
            As[(kq * 4 + 2) * 65 + m] = f.z;
            As[(kq * 4 + 3) * 65 + m] = f.w;
        }
        // Stage B: Bs[k][n] (float4, coalesced)
        #pragma unroll
        for (int s = 0; s < 4; ++s) {
            int idx = tid + s * 256;       // 0..1023
            int k = idx >> 5;
            int c = idx & 31;
            *(float4*)&Bs[k * 128 + c * 4] =
                *(const float4*)&W2[(k0 + k) * Pn + c * 4];
        }
        __syncthreads();

        #pragma unroll
        for (int k = 0; k < 32; ++k) {
            float av[4];
            av[0] = As[k * 65 + ty * 4 + 0];
            av[1] = As[k * 65 + ty * 4 + 1];
            av[2] = As[k * 65 + ty * 4 + 2];
            av[3] = As[k * 65 + ty * 4 + 3];
            float4 bb0 = *(const float4*)&Bs[k * 128 + tx * 8];
            float4 bb1 = *(const float4*)&Bs[k * 128 + tx * 8 + 4];
            float bv[8] = {bb0.x, bb0.y, bb0.z, bb0.w, bb1.x, bb1.y, bb1.z, bb1.w};
            #pragma unroll
            for (int u = 0; u < 4; ++u)
                #pragma unroll
                for (int v = 0; v < 8; ++v)
                    acc[u][v] += av[u] * bv[v];
        }
        __syncthreads();
    }

    #pragma unroll
    for (int u = 0; u < 4; ++u) {
        int row = r0 + ty * 4 + u;
        float4 o0 = {acc[u][0], acc[u][1], acc[u][2], acc[u][3]};
        float4 o1 = {acc[u][4], acc[u][5], acc[u][6], acc[u][7]};
        *(float4*)&g_mw[row * Pn + tx * 8]     = o0;
        *(float4*)&g_mw[row * Pn + tx * 8 + 4] = o1;
    }
}

// ---------------------------------------------------------------------------
// Kernel A: fused sparse aggregation + pos/neg + epilogue
// Grid: (8 j-tiles, 32 batches). 512 threads = 16 warps; warp handles 4 j's.
// adj stored as bytes (exact {0,1} indicator), stride 68 -> conflict-free scan.
// smem ~107 KB -> 2 CTAs/SM -> single wave.
// ---------------------------------------------------------------------------
__global__ __launch_bounds__(512, 2) void agg_kernel(
    const float* __restrict__ adj, const float* __restrict__ weight,
    const float* __restrict__ x, const float* __restrict__ W1,
    float* __restrict__ out) {
    extern __shared__ char smem[];
    float* mwS = (float*)smem;                        // 128*128 f32 (65536 B)
    float* wS  = (float*)(smem + 65536);              // [i][j] stride 64 (32768 B)
    unsigned char* adjB = (unsigned char*)(smem + 98304); // [i][j] stride 68 (8704 B)
    float* W1s = (float*)(smem + 107008);             // 128
    float* vps = W1s + 128;
    float* vns = vps + 128;
    float* cbs = vns + 128;

    int tid = threadIdx.x;
    int warp = tid >> 5;
    int lane = tid & 31;
    int b = blockIdx.y;
    int j0 = blockIdx.x * 64;

    if (tid < 128) {
        W1s[tid] = W1[tid];
        vps[tid] = g_vp[tid];
        vns[tid] = g_vn[tid];
        cbs[tid] = g_cb[tid];
    }

    const float* adj_b = adj + (size_t)b * Nn * Nn;
    const float* w_b   = weight + (size_t)b * Nn * Nn;
    const float* mw_b  = g_mw + (size_t)b * Nn * Pn;

    float4 acc[4];
    float pos[4], neg[4];
    #pragma unroll
    for (int jj = 0; jj < 4; ++jj) {
        acc[jj].x = acc[jj].y = acc[jj].z = acc[jj].w = 0.f;
        pos[jj] = 0.f;
        neg[jj] = 0.f;
    }

    for (int chunk = 0; chunk < 4; ++chunk) {
        int i0 = chunk * 128;
        __syncthreads();  // prev chunk's smem reads done (covers const init too)

        // Stage mw chunk: 128 x 128 floats (float4, coalesced)
        #pragma unroll
        for (int s = 0; s < 8; ++s) {
            int idx = tid + s * 512;      // 0..4095
            int row = idx >> 5;
            int c = idx & 31;
            *(float4*)&mwS[row * 128 + c * 4] =
                *(const float4*)&mw_b[(i0 + row) * Pn + c * 4];
        }
        // Stage weight tile (f32) + adjacency indicator (bytes)
        #pragma unroll
        for (int s = 0; s < 4; ++s) {
            int idx = tid + s * 512;      // 0..2047
            int row = idx >> 4;
            int jc = idx & 15;
            size_t g = (size_t)(i0 + row) * Nn + j0 + jc * 4;
            float4 a = *(const float4*)&adj_b[g];
            float4 w = *(const float4*)&w_b[g];
            *(float4*)&wS[row * 64 + jc * 4] = w;
            uchar4 ab;
            ab.x = (a.x != 0.f);
            ab.y = (a.y != 0.f);
            ab.z = (a.z != 0.f);
            ab.w = (a.w != 0.f);
            *(uchar4*)&adjB[row * 68 + jc * 4] = ab;
        }
        __syncthreads();

        // Warp-cooperative nonzero scan + gather-accumulate
        #pragma unroll
        for (int jj = 0; jj < 4; ++jj) {
            int j = warp * 4 + jj;
            float4 a4 = acc[jj];
            float pj = pos[jj], nj = neg[jj];
            #pragma unroll
            for (int base = 0; base < 128; base += 32) {
                unsigned char av = adjB[(base + lane) * 68 + j];  // stride 17 words: conflict-free
                unsigned m = __ballot_sync(0xffffffffu, av != 0);
                while (m) {
                    int i = base + (__ffs((int)m) - 1);
                    m &= m - 1;
                    float w = wS[i * 64 + j];            // broadcast
                    pj += fmaxf(w, 0.f);
                    nj += fmaxf(-w, 0.f);
                    float4 v = *(const float4*)&mwS[i * 128 + (lane << 2)];
                    a4.x += v.x; a4.y += v.y; a4.z += v.z; a4.w += v.w;
                }
            }
            acc[jj] = a4;
            pos[jj] = pj;
            neg[jj] = nj;
        }
    }

    // Fused epilogue: unit1 + unit2 + unit3 + relu, float4 coalesced store
    #pragma unroll
    for (int jj = 0; jj < 4; ++jj) {
        int gj = j0 + warp * 4 + jj;
        float xv = x[b * Nn + gj];
        int p = lane << 2;
        float4 o;
        o.x = fmaxf(xv * W1s[p + 0] + acc[jj].x + pos[jj] * vps[p + 0] + neg[jj] * vns[p + 0] + cbs[p + 0], 0.f);
        o.y = fmaxf(xv * W1s[p + 1] + acc[jj].y + pos[jj] * vps[p + 1] + neg[jj] * vns[p + 1] + cbs[p + 1], 0.f);
        o.z = fmaxf(xv * W1s[p + 2] + acc[jj].z + pos[jj] * vps[p + 2] + neg[jj] * vns[p + 2] + cbs[p + 2], 0.f);
        o.w = fmaxf(xv * W1s[p + 3] + acc[jj].w + pos[jj] * vps[p + 3] + neg[jj] * vns[p + 3] + cbs[p + 3], 0.f);
        *(float4*)&out[((size_t)b * Nn + gj) * Pn + p] = o;
    }
}

// ---------------------------------------------------------------------------
extern "C" void kernel_launch(void* const* d_in, const int* in_sizes, int n_in,
                              void* d_out, int out_size) {
    const float* x      = (const float*)d_in[0];
    const float* mu     = (const float*)d_in[1];
    const float* weight = (const float*)d_in[2];
    const float* adj    = (const float*)d_in[3];
    const float* W1     = (const float*)d_in[4];
    const float* b1     = (const float*)d_in[5];
    const float* W2     = (const float*)d_in[6];
    const float* b2     = (const float*)d_in[7];
    const float* W3     = (const float*)d_in[8];
    const float* b3     = (const float*)d_in[9];
    const float* theta4 = (const float*)d_in[10];
    float* out = (float*)d_out;

    const int smem_bytes = 107008 + 4 * 128 * 4;   // 109056 B (~107 KB)
    static int configured = -1;
    if (configured < 0) {
        cudaFuncSetAttribute(agg_kernel, cudaFuncAttributeMaxDynamicSharedMemorySize,
                             smem_bytes);
        configured = 1;
    }

    mw_kernel<<<Bn * Nn / 64 + 1, 256>>>(mu, W2, W3, theta4, b1, b2, b3);
    dim3 grid(Nn / 64, Bn);
    agg_kernel<<<grid, 512, smem_bytes>>>(adj, weight, x, W1, out);
}

// round 4
// speedup vs baseline: 1.4844x; 1.1714x over previous
#include <cuda_runtime.h>
#include <stdint.h>

#define Bn 32
#define Nn 512
#define Pn 128

// Scratch (static device globals: allocation-free)
__device__ float g_mw[Bn * Nn * Pn];   // mu @ W2, 8 MB
__device__ float g_vp[Pn];
__device__ float g_vn[Pn];
__device__ float g_cb[Pn];             // b1 + b2 + b3

// ---- packed f32x2 helpers (sm_100 packed-FP32 pipe; PTX-only) -------------
__device__ __forceinline__ void fma2(unsigned long long& d,
                                     unsigned long long a,
                                     unsigned long long b) {
    asm("fma.rn.f32x2 %0, %1, %2, %3;" : "=l"(d) : "l"(a), "l"(b), "l"(d));
}
__device__ __forceinline__ void add2(unsigned long long& d,
                                     unsigned long long v) {
    asm("add.rn.f32x2 %0, %1, %2;" : "=l"(d) : "l"(d), "l"(v));
}
__device__ __forceinline__ unsigned long long rep2(float a) {
    unsigned long long p;
    asm("mov.b64 %0, {%1, %1};" : "=l"(p) : "f"(a));
    return p;
}
__device__ __forceinline__ float2 unpack2(unsigned long long p) {
    float2 r;
    asm("mov.b64 {%0, %1}, %2;" : "=f"(r.x), "=f"(r.y) : "l"(p));
    return r;
}

// ---------------------------------------------------------------------------
// Kernel M: g_mw = mu @ W2, fp32 via packed f32x2. Last block does prep.
// ---------------------------------------------------------------------------
__global__ __launch_bounds__(256) void mw_kernel(const float* __restrict__ mu,
                                                 const float* __restrict__ W2,
                                                 const float* __restrict__ W3,
                                                 const float* __restrict__ theta4,
                                                 const float* __restrict__ b1,
                                                 const float* __restrict__ b2,
                                                 const float* __restrict__ b3) {
    if (blockIdx.x == gridDim.x - 1) {
        int p = threadIdx.x;
        if (p < Pn) {
            float vp = 0.f, vn = 0.f;
            #pragma unroll 8
            for (int q = 0; q < Pn; ++q) {
                float t = theta4[q];
                float w = W3[q * Pn + p];
                vp += fmaxf(t, 0.f) * w;
                vn += fmaxf(-t, 0.f) * w;
            }
            g_vp[p] = vp;
            g_vn[p] = vn;
            g_cb[p] = b1[p] + b2[p] + b3[p];
        }
        return;
    }

    __shared__ float As[32 * 68];    // [k][m], pad 68 (16B-aligned float4 rows)
    __shared__ float Bs[32 * 128];   // [k][n]

    int tid = threadIdx.x;
    int tx = tid & 15;   // 16 col-groups of 8
    int ty = tid >> 4;   // 16 row-groups of 4
    int r0 = blockIdx.x * 64;

    unsigned long long acc2[4][4];   // [row u][col-pair q] -> (p2q, p2q+1)
    #pragma unroll
    for (int u = 0; u < 4; ++u)
        #pragma unroll
        for (int q = 0; q < 4; ++q) acc2[u][q] = 0ull;

    for (int kb = 0; kb < 4; ++kb) {
        int k0 = kb * 32;
        #pragma unroll
        for (int s = 0; s < 2; ++s) {
            int idx = tid + s * 256;           // 0..511
            int m = idx >> 3;                  // 0..63
            int kq = idx & 7;                  // k-quad
            float4 f = *(const float4*)&mu[(r0 + m) * Pn + k0 + kq * 4];
            As[(kq * 4 + 0) * 68 + m] = f.x;
            As[(kq * 4 + 1) * 68 + m] = f.y;
            As[(kq * 4 + 2) * 68 + m] = f.z;
            As[(kq * 4 + 3) * 68 + m] = f.w;
        }
        #pragma unroll
        for (int s = 0; s < 4; ++s) {
            int idx = tid + s * 256;
            int k = idx >> 5;
            int c = idx & 31;
            *(float4*)&Bs[k * 128 + c * 4] =
                *(const float4*)&W2[(k0 + k) * Pn + c * 4];
        }
        __syncthreads();

        #pragma unroll
        for (int k = 0; k < 32; ++k) {
            float4 a4 = *(const float4*)&As[k * 68 + ty * 4];
            ulonglong2 B0 = *(const ulonglong2*)&Bs[k * 128 + tx * 8];
            ulonglong2 B1 = *(const ulonglong2*)&Bs[k * 128 + tx * 8 + 4];
            unsigned long long pa[4] = {rep2(a4.x), rep2(a4.y), rep2(a4.z), rep2(a4.w)};
            #pragma unroll
            for (int u = 0; u < 4; ++u) {
                fma2(acc2[u][0], pa[u], B0.x);
                fma2(acc2[u][1], pa[u], B0.y);
                fma2(acc2[u][2], pa[u], B1.x);
                fma2(acc2[u][3], pa[u], B1.y);
            }
        }
        __syncthreads();
    }

    #pragma unroll
    for (int u = 0; u < 4; ++u) {
        int row = r0 + ty * 4 + u;
        ulonglong2 o0 = {acc2[u][0], acc2[u][1]};
        ulonglong2 o1 = {acc2[u][2], acc2[u][3]};
        *(ulonglong2*)&g_mw[row * Pn + tx * 8]     = o0;
        *(ulonglong2*)&g_mw[row * Pn + tx * 8 + 4] = o1;
    }
}

// ---------------------------------------------------------------------------
// Kernel A: fused sparse aggregation + dense pos/neg + epilogue
// Grid: (8 j-tiles, 32 batches), 512 threads.
// smem: mwS 64KB | adjB 8.7KB | consts+posS/negS ~2.5KB  (~77KB -> 2 CTA/SM)
// pos/neg: register partials during staging, reduced via buffer overlaid on mwS.
// ---------------------------------------------------------------------------
__global__ __launch_bounds__(512, 2) void agg_kernel(
    const float* __restrict__ adj, const float* __restrict__ weight,
    const float* __restrict__ x, const float* __restrict__ W1,
    float* __restrict__ out) {
    extern __shared__ char smem[];
    float* mwS = (float*)smem;                            // 128*128 f32
    unsigned char* adjB = (unsigned char*)(smem + 65536); // [i][j] stride 68
    float* W1s  = (float*)(smem + 74240);                 // 128
    float* vps  = W1s + 128;
    float* vns  = vps + 128;
    float* cbs  = vns + 128;
    float* posS = cbs + 128;                              // 64
    float* negS = posS + 64;                              // 64
    float* pbuf = (float*)smem;                           // overlay (phase 2)

    int tid = threadIdx.x;
    int warp = tid >> 5;
    int lane = tid & 31;
    int b = blockIdx.y;
    int j0 = blockIdx.x * 64;

    if (tid < 128) {
        W1s[tid] = W1[tid];
        vps[tid] = g_vp[tid];
        vns[tid] = g_vn[tid];
        cbs[tid] = g_cb[tid];
    }

    const float* adj_b = adj + (size_t)b * Nn * Nn;
    const float* w_b   = weight + (size_t)b * Nn * Nn;
    const float* mw_b  = g_mw + (size_t)b * Nn * Pn;

    unsigned long long acc2[4][2];
    float posr[4], negr[4];
    #pragma unroll
    for (int jj = 0; jj < 4; ++jj) {
        acc2[jj][0] = 0ull;
        acc2[jj][1] = 0ull;
        posr[jj] = 0.f;
        negr[jj] = 0.f;
    }

    for (int chunk = 0; chunk < 4; ++chunk) {
        int i0 = chunk * 128;
        __syncthreads();  // prev chunk smem reads done (covers const init too)

        // Stage mw chunk: 128 x 128 floats
        #pragma unroll
        for (int s = 0; s < 8; ++s) {
            int idx = tid + s * 512;
            int row = idx >> 5;
            int c = idx & 31;
            *(float4*)&mwS[row * 128 + c * 4] =
                *(const float4*)&mw_b[(i0 + row) * Pn + c * 4];
        }
        // Stage adjacency bytes + accumulate pos/neg register partials.
        // Thread's columns: jc*4..+3 with jc = tid&15 (fixed across s, chunks).
        #pragma unroll
        for (int s = 0; s < 4; ++s) {
            int idx = tid + s * 512;
            int row = idx >> 4;
            int jc = idx & 15;
            size_t g = (size_t)(i0 + row) * Nn + j0 + jc * 4;
            float4 a = *(const float4*)&adj_b[g];
            float4 w = *(const float4*)&w_b[g];
            uchar4 ab;
            ab.x = (a.x != 0.f);
            ab.y = (a.y != 0.f);
            ab.z = (a.z != 0.f);
            ab.w = (a.w != 0.f);
            *(uchar4*)&adjB[row * 68 + jc * 4] = ab;
            // adj is exactly {0,1}: pos += adj * relu(w)  (bit-exact masking)
            posr[0] += a.x * fmaxf(w.x, 0.f);  negr[0] += a.x * fmaxf(-w.x, 0.f);
            posr[1] += a.y * fmaxf(w.y, 0.f);  negr[1] += a.y * fmaxf(-w.y, 0.f);
            posr[2] += a.z * fmaxf(w.z, 0.f);  negr[2] += a.z * fmaxf(-w.z, 0.f);
            posr[3] += a.w * fmaxf(w.w, 0.f);  negr[3] += a.w * fmaxf(-w.w, 0.f);
        }
        __syncthreads();

        // Warp-cooperative nonzero scan + gather-accumulate (f32x2 packed)
        #pragma unroll
        for (int jj = 0; jj < 4; ++jj) {
            int j = warp * 4 + jj;
            #pragma unroll
            for (int base = 0; base < 128; base += 32) {
                unsigned char av = adjB[(base + lane) * 68 + j];  // conflict-free
                unsigned m = __ballot_sync(0xffffffffu, av != 0);
                while (m) {
                    int i = base + (__ffs((int)m) - 1);
                    m &= m - 1;
                    ulonglong2 v = *(const ulonglong2*)&mwS[i * 128 + (lane << 2)];
                    add2(acc2[jj][0], v.x);
                    add2(acc2[jj][1], v.y);
                }
            }
        }
    }

    // Phase 2: reduce pos/neg partials (buffer overlays mwS, now dead)
    __syncthreads();
    {
        int g = tid >> 4;        // 0..31
        int jc = tid & 15;
        #pragma unroll
        for (int c = 0; c < 4; ++c) {
            pbuf[g * 64 + jc * 4 + c]        = posr[c];
            pbuf[2048 + g * 64 + jc * 4 + c] = negr[c];
        }
    }
    __syncthreads();
    if (tid < 128) {
        int j = tid & 63;
        const float* src = pbuf + (tid < 64 ? 0 : 2048);
        float s = 0.f;
        #pragma unroll
        for (int g = 0; g < 32; ++g) s += src[g * 64 + j];
        if (tid < 64) posS[j] = s; else negS[j] = s;
    }
    __syncthreads();

    // Fused epilogue
    #pragma unroll
    for (int jj = 0; jj < 4; ++jj) {
        int gj = j0 + warp * 4 + jj;
        float xv = x[b * Nn + gj];
        float pj = posS[warp * 4 + jj];
        float nj = negS[warp * 4 + jj];
        int p = lane << 2;
        float2 u0 = unpack2(acc2[jj][0]);
        float2 u1 = unpack2(acc2[jj][1]);
        float4 o;
        o.x = fmaxf(xv * W1s[p + 0] + u0.x + pj * vps[p + 0] + nj * vns[p + 0] + cbs[p + 0], 0.f);
        o.y = fmaxf(xv * W1s[p + 1] + u0.y + pj * vps[p + 1] + nj * vns[p + 1] + cbs[p + 1], 0.f);
        o.z = fmaxf(xv * W1s[p + 2] + u1.x + pj * vps[p + 2] + nj * vns[p + 2] + cbs[p + 2], 0.f);
        o.w = fmaxf(xv * W1s[p + 3] + u1.y + pj * vps[p + 3] + nj * vns[p + 3] + cbs[p + 3], 0.f);
        *(float4*)&out[((size_t)b * Nn + gj) * Pn + p] = o;
    }
}

// ---------------------------------------------------------------------------
extern "C" void kernel_launch(void* const* d_in, const int* in_sizes, int n_in,
                              void* d_out, int out_size) {
    const float* x      = (const float*)d_in[0];
    const float* mu     = (const float*)d_in[1];
    const float* weight = (const float*)d_in[2];
    const float* adj    = (const float*)d_in[3];
    const float* W1     = (const float*)d_in[4];
    const float* b1     = (const float*)d_in[5];
    const float* W2     = (const float*)d_in[6];
    const float* b2     = (const float*)d_in[7];
    const float* W3     = (const float*)d_in[8];
    const float* b3     = (const float*)d_in[9];
    const float* theta4 = (const float*)d_in[10];
    float* out = (float*)d_out;

    const int smem_bytes = 74240 + 4 * 128 * 4 + 2 * 64 * 4;  // 76800 B
    static int configured = -1;
    if (configured < 0) {
        cudaFuncSetAttribute(agg_kernel, cudaFuncAttributeMaxDynamicSharedMemorySize,
                             smem_bytes);
        configured = 1;
    }

    mw_kernel<<<Bn * Nn / 64 + 1, 256>>>(mu, W2, W3, theta4, b1, b2, b3);
    dim3 grid(Nn / 64, Bn);
    agg_kernel<<<grid, 512, smem_bytes>>>(adj, weight, x, W1, out);
}